// round 2
// baseline (speedup 1.0000x reference)
#include <cuda_runtime.h>

// out[i] = sum_j relu(adj[i,j] * Linv[i,j]) * W[j] + b
// N = 8192. Inputs: d_in[0]=x_e (unused), d_in[1]=Linv, d_in[2]=adjacency,
// d_in[3]=W (N floats), d_in[4]=b (1 float). Output: N floats ([N,1]).

#define N_DIM 8192
#define THREADS 256

__global__ __launch_bounds__(THREADS)
void dist2cycle_rowdot_kernel(const float4* __restrict__ Linv,
                              const float4* __restrict__ adj,
                              const float4* __restrict__ W4,
                              const float*  __restrict__ bptr,
                              float* __restrict__ out) {
    const int row = blockIdx.x;
    const size_t base = (size_t)row * (N_DIM / 4);
    const float4* __restrict__ L = Linv + base;
    const float4* __restrict__ A = adj  + base;

    float acc = 0.0f;

    // 8192/4 = 2048 float4 per row; 256 threads -> 8 iterations.
    #pragma unroll 8
    for (int j = threadIdx.x; j < N_DIM / 4; j += THREADS) {
        float4 l = __ldg(&L[j]);
        float4 a = __ldg(&A[j]);
        float4 w = __ldg(&W4[j]);
        acc = fmaf(fmaxf(a.x * l.x, 0.0f), w.x, acc);
        acc = fmaf(fmaxf(a.y * l.y, 0.0f), w.y, acc);
        acc = fmaf(fmaxf(a.z * l.z, 0.0f), w.z, acc);
        acc = fmaf(fmaxf(a.w * l.w, 0.0f), w.w, acc);
    }

    // Warp reduce
    #pragma unroll
    for (int off = 16; off > 0; off >>= 1)
        acc += __shfl_xor_sync(0xFFFFFFFFu, acc, off);

    // Block reduce across 8 warps
    __shared__ float warp_sums[THREADS / 32];
    const int lane = threadIdx.x & 31;
    const int wid  = threadIdx.x >> 5;
    if (lane == 0) warp_sums[wid] = acc;
    __syncthreads();

    if (wid == 0) {
        float v = (lane < THREADS / 32) ? warp_sums[lane] : 0.0f;
        #pragma unroll
        for (int off = 4; off > 0; off >>= 1)
            v += __shfl_xor_sync(0xFFFFFFFFu, v, off);
        if (lane == 0)
            out[row] = v + __ldg(bptr);
    }
}

extern "C" void kernel_launch(void* const* d_in, const int* in_sizes, int n_in,
                              void* d_out, int out_size) {
    // metadata order: x_e, Linv, adjacency, W, b
    const float4* Linv = (const float4*)d_in[1];
    const float4* adj  = (const float4*)d_in[2];
    const float4* W4   = (const float4*)d_in[3];
    const float*  b    = (const float*)d_in[4];
    float* out = (float*)d_out;

    dist2cycle_rowdot_kernel<<<N_DIM, THREADS>>>(Linv, adj, W4, b, out);
}